// round 4
// baseline (speedup 1.0000x reference)
#include <cuda_runtime.h>
#include <cstdint>

// Problem constants
#define TT 131072
#define BB 6
#define II 32
#define HH 3
#define LL 8
#define G3 9                      // 3*H gate rows
#define BH (BB * HH)              // 18
#define CHUNK 32
#define NCH (TT / CHUNK)          // 4096 chunks
#define XGF (CHUNK * BB * G3)     // 1728 floats per layer-0 input chunk
#define PREG_N (XGF / 32)         // 54 per lane

// Scratch for layer-0 input projections: (T, B, 9)
__device__ float g_xg0[(size_t)TT * BB * G3];

__device__ __forceinline__ float ftanh(float x) {
    float r; asm("tanh.approx.f32 %0, %1;" : "=f"(r) : "f"(x)); return r;
}
__device__ __forceinline__ uint32_t smem_u32(const void* p) {
    uint32_t a;
    asm("{ .reg .u64 t; cvta.to.shared.u64 t, %1; cvt.u32.u64 %0, t; }"
        : "=r"(a) : "l"(p));
    return a;
}
__device__ __forceinline__ uint32_t mapa_sh(uint32_t addr, uint32_t rank) {
    uint32_t r;
    asm("mapa.shared::cluster.u32 %0, %1, %2;" : "=r"(r) : "r"(addr), "r"(rank));
    return r;
}
__device__ __forceinline__ void st_cluster_f32(uint32_t addr, float v) {
    asm volatile("st.shared::cluster.f32 [%0], %1;" :: "r"(addr), "f"(v));
}
__device__ __forceinline__ void cluster_sync_() {
    asm volatile("barrier.cluster.arrive.aligned;" ::: "memory");
    asm volatile("barrier.cluster.wait.aligned;" ::: "memory");
}

// ---------------------------------------------------------------------------
// Kernel A: xg0[t,b,g] = x[t,b,:] . w_ih0[g,:] + b_ih[0,g]   (memory-bound)
// ---------------------------------------------------------------------------
__global__ void __launch_bounds__(256) proj0_kernel(
    const float* __restrict__ x, const float* __restrict__ w_ih0,
    const float* __restrict__ b_ih)
{
    __shared__ float ws[G3 * II];
    __shared__ float bs[G3];
    for (int i = threadIdx.x; i < G3 * II; i += blockDim.x) ws[i] = w_ih0[i];
    if (threadIdx.x < G3) bs[threadIdx.x] = b_ih[threadIdx.x];
    __syncthreads();

    int idx = blockIdx.x * blockDim.x + threadIdx.x;  // (t*B + b)
    if (idx >= TT * BB) return;

    float xv[II];
    const float4* xp = (const float4*)(x + (size_t)idx * II);
#pragma unroll
    for (int q = 0; q < II / 4; ++q) {
        float4 v = xp[q];
        xv[q * 4 + 0] = v.x; xv[q * 4 + 1] = v.y;
        xv[q * 4 + 2] = v.z; xv[q * 4 + 3] = v.w;
    }
    float* o = g_xg0 + (size_t)idx * G3;
#pragma unroll
    for (int g = 0; g < G3; ++g) {
        float acc = bs[g];
#pragma unroll
        for (int k = 0; k < II; ++k) acc = fmaf(xv[k], ws[g * II + k], acc);
        o[g] = acc;
    }
}

// One GRU cell step for lane's (batch bc, unit jc).
//   sigma(x) = 0.5*tanh(0.5x)+0.5 ;  h' = (1-z)n + z h
#define GRU_STEP()                                                          \
    {                                                                       \
        float hA = __shfl_sync(0xffffffffu, h, srcA);                       \
        float hB = __shfl_sync(0xffffffffu, h, srcB);                       \
        float pr = fmaf(hB, whr2, fmaf(hA, whr1, fmaf(h, whr0, pr0)));      \
        float pz = fmaf(hB, whz2, fmaf(hA, whz1, fmaf(h, whz0, pz0)));      \
        float hn = fmaf(hB, whn2, fmaf(hA, whn1, fmaf(h, whn0, Bhn)));      \
        float tr = ftanh(0.5f * pr);                                        \
        float tz = ftanh(0.5f * pz);                                        \
        float hnh = 0.5f * hn;                                              \
        float cc  = fmaf(0.5f, hn, xn_);                                    \
        float a   = fmaf(tr, hnh, cc);                                      \
        float nn  = ftanh(a);                                               \
        float z   = fmaf(0.5f, tz, 0.5f);                                   \
        float omz = fmaf(-0.5f, tz, 0.5f);                                  \
        float zh  = z * h;                                                  \
        h = fmaf(omz, nn, zh);                                              \
    }

// ---------------------------------------------------------------------------
// Kernel B: 8-CTA cluster, one warp (= one GRU layer) per CTA / per SM.
//   lane = b*4 + j : batch b (0..5), hidden unit j (0..2).
//   Round k: CTA l computes chunk c = k - l from its OWN hbuf[rp] (written by
//   CTA l-1 last round via DSMEM), writes results into CTA l+1's hbuf[wp].
//   Round boundary: cluster barrier (release/acquire orders DSMEM stores).
// ---------------------------------------------------------------------------
__global__ void __launch_bounds__(32, 1) __cluster_dims__(LL, 1, 1)
gru_cluster_kernel(
    const float* __restrict__ hxs,  const float* __restrict__ w_ihR,
    const float* __restrict__ w_hh, const float* __restrict__ b_ih,
    const float* __restrict__ b_hh, float* __restrict__ out)
{
    __shared__ float hbuf[2][CHUNK][BH];   // input chunks (filled by layer l-1)
    __shared__ float xin[XGF];             // layer-0 staged inputs (CTA 0 only)

    const int l    = blockIdx.x;           // layer == cluster rank
    const int lane = threadIdx.x;
    const int b = lane >> 2, j = lane & 3;
    const int bc = (b > 5) ? 5 : b;
    const int jc = (j > 2) ? 2 : j;
    const bool valid = (j < 3) && (b < 6);
    const int j1 = (jc + 1 == 3) ? 0 : jc + 1;
    const int j2 = (j1 + 1 == 3) ? 0 : j1 + 1;
    const int srcA = (lane & ~3) + j1;
    const int srcB = (lane & ~3) + j2;
    const int sidx = bc * 3 + jc;

    // DSMEM pointer to the NEXT layer's hbuf (same smem offset in peer CTA)
    const uint32_t hbuf_local = smem_u32(&hbuf[0][0][0]);
    const uint32_t peer_base  = (l < LL - 1) ? mapa_sh(hbuf_local, l + 1) : 0;

    // --- per-lane weights: recurrent rows (r,z,n of unit jc), columns
    // permuted to (self=jc, j1, j2) to match shfl arrival order ---
    const float* W = w_hh + l * G3 * HH;
    const int rr = jc, rz = 3 + jc, rn = 6 + jc;
    float whr0 = W[rr*3+jc], whr1 = W[rr*3+j1], whr2 = W[rr*3+j2];
    float whz0 = W[rz*3+jc], whz1 = W[rz*3+j1], whz2 = W[rz*3+j2];
    float whn0 = W[rn*3+jc], whn1 = W[rn*3+j1], whn2 = W[rn*3+j2];

    float wir0 = 0, wir1 = 0, wir2 = 0, wiz0 = 0, wiz1 = 0, wiz2 = 0;
    float win0 = 0, win1 = 0, win2 = 0;
    if (l > 0) {
        const float* Wi = w_ihR + (l - 1) * G3 * HH;
        wir0 = Wi[rr*3+0]; wir1 = Wi[rr*3+1]; wir2 = Wi[rr*3+2];
        wiz0 = Wi[rz*3+0]; wiz1 = Wi[rz*3+1]; wiz2 = Wi[rz*3+2];
        win0 = Wi[rn*3+0]; win1 = Wi[rn*3+1]; win2 = Wi[rn*3+2];
    }
    const float Br  = b_hh[l*G3 + rr] + ((l > 0) ? b_ih[l*G3 + rr] : 0.0f);
    const float Bz  = b_hh[l*G3 + rz] + ((l > 0) ? b_ih[l*G3 + rz] : 0.0f);
    const float Bxn = (l > 0) ? b_ih[l*G3 + rn] : 0.0f;
    const float Bhn = b_hh[l*G3 + rn];

    float h = hxs[l * BH + sidx];

    // Layer 0: register prefetch of xg chunks.
    float preg[PREG_N];
    if (l == 0) {
#pragma unroll
        for (int q = 0; q < PREG_N; ++q)
            preg[q] = g_xg0[lane + 32 * q];   // chunk 0
    }

    const int NR = NCH + LL - 1;
    for (int k = 0; k < NR; ++k) {
        const int c  = k - l;
        const int wp = k & 1;
        const int rp = wp ^ 1;
        const bool run = ((unsigned)c < (unsigned)NCH);

        if (run) {
            // Per-round output cursors
            uint32_t pdst = peer_base + (uint32_t)(wp * CHUNK * BH + sidx) * 4u;
            float* gdst = out + (size_t)(c * CHUNK) * BH + sidx;

            if (l == 0) {
                // dump prefetched chunk c to xin, start prefetch of c+1
#pragma unroll
                for (int q = 0; q < PREG_N; ++q)
                    xin[lane + 32 * q] = preg[q];
                __syncwarp();
                if (c + 1 < NCH) {
                    const float* src = g_xg0 + (size_t)(c + 1) * XGF;
#pragma unroll
                    for (int q = 0; q < PREG_N; ++q)
                        preg[q] = src[lane + 32 * q];
                }
                const float* xp = xin + bc * 9;
#pragma unroll 4
                for (int s = 0; s < CHUNK; ++s) {
                    float pr0 = xp[jc]     + Br;   // xg0 already holds b_ih
                    float pz0 = xp[3 + jc] + Bz;
                    float xn_ = xp[6 + jc];
                    xp += BB * G3;
                    GRU_STEP();
                    if (valid) st_cluster_f32(pdst, h);
                    pdst += BH * 4;
                }
            } else {
                const float* ip = &hbuf[rp][0][bc * 3];
#pragma unroll 4
                for (int s = 0; s < CHUNK; ++s) {
                    float i0 = ip[0], i1 = ip[1], i2 = ip[2];
                    ip += BH;
                    float pr0 = fmaf(i2, wir2, fmaf(i1, wir1, fmaf(i0, wir0, Br)));
                    float pz0 = fmaf(i2, wiz2, fmaf(i1, wiz1, fmaf(i0, wiz0, Bz)));
                    float xn_ = fmaf(i2, win2, fmaf(i1, win1, fmaf(i0, win0, Bxn)));
                    GRU_STEP();
                    if (valid) {
                        if (l < LL - 1) st_cluster_f32(pdst, h);
                        else            *gdst = h;
                    }
                    pdst += BH * 4;
                    gdst += BH;
                }
            }

            // Final hidden state of this layer: (L,B,H) tail.
            if (c == NCH - 1 && valid)
                out[(size_t)TT * BH + l * BH + sidx] = h;
        }

        cluster_sync_();
    }
}

// ---------------------------------------------------------------------------
// Launch: inputs in metadata order: x, hxs, w_ih0, w_ihR, w_hh, b_ih, b_hh.
// Output: out (T,B,H) followed by finals (L,B,H).
// ---------------------------------------------------------------------------
extern "C" void kernel_launch(void* const* d_in, const int* in_sizes, int n_in,
                              void* d_out, int out_size) {
    const float* x     = (const float*)d_in[0];
    const float* hxs   = (const float*)d_in[1];
    const float* w_ih0 = (const float*)d_in[2];
    const float* w_ihR = (const float*)d_in[3];
    const float* w_hh  = (const float*)d_in[4];
    const float* b_ih  = (const float*)d_in[5];
    const float* b_hh  = (const float*)d_in[6];
    float* out = (float*)d_out;

    const int nrows = TT * BB;
    proj0_kernel<<<(nrows + 255) / 256, 256>>>(x, w_ih0, b_ih);
    gru_cluster_kernel<<<LL, 32>>>(hxs, w_ihR, w_hh, b_ih, b_hh, out);
}